// round 14
// baseline (speedup 1.0000x reference)
#include <cuda_runtime.h>
#include <cuda_bf16.h>
#include <math.h>
#include <stdint.h>

typedef __nv_bfloat16 bf16;

// Problem constants
#define Bz   4
#define Cc   64
#define Hh   256
#define Ww   256
#define HW   65536
#define HEADS 2
#define CH   32
#define WS   8
#define HID  170
#define C2   340
#define C3   192

// ---------------- scratch (device globals) ----------------
static __device__ bf16  g_qkv [(size_t)Bz*C3*HW];
static __device__ bf16  g_qkv2[(size_t)Bz*C3*HW];
static __device__ float g_x1  [(size_t)Bz*Cc*HW];       // residual carrier: fp32
static __device__ bf16  g_mid [(size_t)Bz*C2*HW];
static __device__ bf16  g_y   [(size_t)Bz*HID*HW];
// pre-packed bf16 weights, [o][k] pairs (uint32 = 2 k-consecutive bf16)
static __device__ uint32_t g_wqb[192 * 32];
static __device__ uint32_t g_wpb[384 * 32];
static __device__ uint32_t g_wob[64 * 96];

// ---------------- helpers ----------------
__device__ __forceinline__ void mma_bf16(float* c,
        uint32_t a0, uint32_t a1, uint32_t a2, uint32_t a3,
        uint32_t b0, uint32_t b1)
{
    asm volatile("mma.sync.aligned.m16n8k16.row.col.f32.bf16.bf16.f32 "
        "{%0,%1,%2,%3}, {%4,%5,%6,%7}, {%8,%9}, {%0,%1,%2,%3};"
        : "+f"(c[0]), "+f"(c[1]), "+f"(c[2]), "+f"(c[3])
        : "r"(a0), "r"(a1), "r"(a2), "r"(a3), "r"(b0), "r"(b1));
}

__device__ __forceinline__ void ldmx4t(uint32_t* a, uint32_t saddr) {
    asm volatile("ldmatrix.sync.aligned.m8n8.x4.trans.shared.b16 {%0,%1,%2,%3}, [%4];"
        : "=r"(a[0]), "=r"(a[1]), "=r"(a[2]), "=r"(a[3]) : "r"(saddr));
}

__device__ __forceinline__ uint32_t packbf(float x, float y) {
    __nv_bfloat162 t = __float22bfloat162_rn(make_float2(x, y));
    return *reinterpret_cast<uint32_t*>(&t);
}

__device__ __forceinline__ void bf8_to_f(const uint4& u, float* f) {
    float2 t;
    t = __bfloat1622float2(*reinterpret_cast<const __nv_bfloat162*>(&u.x)); f[0]=t.x; f[1]=t.y;
    t = __bfloat1622float2(*reinterpret_cast<const __nv_bfloat162*>(&u.y)); f[2]=t.x; f[3]=t.y;
    t = __bfloat1622float2(*reinterpret_cast<const __nv_bfloat162*>(&u.z)); f[4]=t.x; f[5]=t.y;
    t = __bfloat1622float2(*reinterpret_cast<const __nv_bfloat162*>(&u.w)); f[6]=t.x; f[7]=t.y;
}
__device__ __forceinline__ uint4 f_to_bf8(const float* f) {
    uint4 u;
    *reinterpret_cast<__nv_bfloat162*>(&u.x) = __float22bfloat162_rn(make_float2(f[0], f[1]));
    *reinterpret_cast<__nv_bfloat162*>(&u.y) = __float22bfloat162_rn(make_float2(f[2], f[3]));
    *reinterpret_cast<__nv_bfloat162*>(&u.z) = __float22bfloat162_rn(make_float2(f[4], f[5]));
    *reinterpret_cast<__nv_bfloat162*>(&u.w) = __float22bfloat162_rn(make_float2(f[6], f[7]));
    return u;
}

// ---------------- K0: weight prep (pack bf16 [o][k]) --------------------------
__global__ void __launch_bounds__(256) k_prep(const float* __restrict__ qkvw,
        const float* __restrict__ pinw, const float* __restrict__ poutw,
        uint32_t* __restrict__ wqb, uint32_t* __restrict__ wpb,
        uint32_t* __restrict__ wob)
{
    const int t = blockIdx.x * 256 + threadIdx.x;
    if (t < 192 * 32) {
        const int o = t >> 5, kw = t & 31;
        wqb[t] = packbf(qkvw[o * 64 + 2 * kw], qkvw[o * 64 + 2 * kw + 1]);
    }
    if (t < 384 * 32) {
        const int o = t >> 5, kw = t & 31;
        wpb[t] = (o < C2) ? packbf(pinw[o * 64 + 2 * kw], pinw[o * 64 + 2 * kw + 1]) : 0u;
    }
    if (t < 64 * 96) {
        const int o = t / 96, kw = t % 96;
        const int k0 = 2 * kw;
        const float v0 = (k0     < HID) ? poutw[o * HID + k0]     : 0.f;
        const float v1 = (k0 + 1 < HID) ? poutw[o * HID + k0 + 1] : 0.f;
        wob[t] = packbf(v0, v1);
    }
}

// ---------------- K1/K3: fused LayerNorm + 1x1 conv, bf16 MMA -----------------
template<int COUT>
__global__ void __launch_bounds__(256) k_ln_bf16(const float* __restrict__ xin,
        const float* __restrict__ gw, const float* __restrict__ gb,
        const uint32_t* __restrict__ wb, bf16* __restrict__ out)
{
    __shared__ uint32_t sx[128 * 36];
    __shared__ uint32_t ws[64 * 36];

    const int tid  = threadIdx.x;
    const int lane = tid & 31;
    const int warp = tid >> 5;
    const int r    = lane >> 2;
    const int c4   = lane & 3;
    const int p0   = blockIdx.x * 128;
    const int b    = p0 >> 16;
    const int hw0  = p0 & 65535;

    {
        const int pl = tid >> 1, half = tid & 1;
        const float* xp = xin + (size_t)(b * 64 + half * 32) * HW + hw0 + pl;
        float xv[32];
        float s = 0.f, s2 = 0.f;
#pragma unroll
        for (int i = 0; i < 32; i++) {
            xv[i] = xp[(size_t)i * HW];
            s += xv[i]; s2 += xv[i] * xv[i];
        }
        s  += __shfl_xor_sync(0xffffffffu, s, 1);
        s2 += __shfl_xor_sync(0xffffffffu, s2, 1);
        const float mu   = s * (1.f / 64.f);
        const float var  = fmaxf(s2 * (1.f / 64.f) - mu * mu, 0.f);
        const float rstd = rsqrtf(var + 1e-5f);
        uint32_t* sxp = sx + pl * 36 + half * 16;
#pragma unroll
        for (int i2 = 0; i2 < 16; i2++) {
            const int c = half * 32 + 2 * i2;
            const float v0 = (xv[2*i2]   - mu) * rstd * __ldg(&gw[c])   + __ldg(&gb[c]);
            const float v1 = (xv[2*i2+1] - mu) * rstd * __ldg(&gw[c+1]) + __ldg(&gb[c+1]);
            sxp[i2] = packbf(v0, v1);
        }
    }
    __syncthreads();

    const uint32_t* ap = sx + (warp * 16 + r) * 36 + c4;
    uint32_t areg[4][4];
#pragma unroll
    for (int kk = 0; kk < 4; kk++) {
        const int kb = kk * 8;
        areg[kk][0] = ap[kb];
        areg[kk][1] = ap[8 * 36 + kb];
        areg[kk][2] = ap[kb + 4];
        areg[kk][3] = ap[8 * 36 + kb + 4];
    }

    const int pixb = hw0 + warp * 16 + r;
    const bool evenr = (r & 1) == 0;
    const int NCH  = (COUT + 63) / 64;
    for (int chunk = 0; chunk < NCH; chunk++) {
        const int och = chunk * 64;
        __syncthreads();
        for (int idx = tid; idx < 2048; idx += 256) {
            const int o = idx >> 5, kw = idx & 31;
            ws[o * 36 + kw] = wb[(och + o) * 32 + kw];
        }
        __syncthreads();

        float acc[8][4];
#pragma unroll
        for (int nt = 0; nt < 8; nt++)
#pragma unroll
            for (int j = 0; j < 4; j++) acc[nt][j] = 0.f;

#pragma unroll
        for (int kk = 0; kk < 4; kk++) {
            const int kb = kk * 8 + c4;
#pragma unroll
            for (int nt = 0; nt < 8; nt++) {
                const uint32_t b0 = ws[(nt * 8 + r) * 36 + kb];
                const uint32_t b1 = ws[(nt * 8 + r) * 36 + kb + 4];
                mma_bf16(acc[nt], areg[kk][0], areg[kk][1], areg[kk][2], areg[kk][3],
                         b0, b1);
            }
        }

        // ---- packed store epilogue: shfl pixel-pair exchange -> STG.32
#pragma unroll
        for (int nt = 0; nt < 8; nt++) {
            const int o = och + nt * 8 + 2 * c4;
            const float pc0 = __shfl_xor_sync(0xffffffffu, acc[nt][0], 4);
            const float pc1 = __shfl_xor_sync(0xffffffffu, acc[nt][1], 4);
            const float pc2 = __shfl_xor_sync(0xffffffffu, acc[nt][2], 4);
            const float pc3 = __shfl_xor_sync(0xffffffffu, acc[nt][3], 4);
            if (evenr) {
                if ((COUT & 63) == 0 || o < COUT) {
                    uint32_t* p = (uint32_t*)(out + (size_t)(b * COUT + o) * HW + pixb);
                    p[0] = packbf(acc[nt][0], pc0);
                    p[4] = packbf(acc[nt][2], pc2);
                }
            } else {
                if ((COUT & 63) == 0 || o + 1 < COUT) {
                    uint32_t* p = (uint32_t*)(out + (size_t)(b * COUT + o + 1) * HW + pixb - 1);
                    p[0] = packbf(pc1, acc[nt][1]);
                    p[4] = packbf(pc3, acc[nt][3]);
                }
            }
        }
    }
}

// ---------------- K5: pout (64 x 170) bf16 MMA + residual ----------------------
__global__ void __launch_bounds__(256) k_pout_bf16(const bf16* __restrict__ y,
        const uint32_t* __restrict__ wob, const float* __restrict__ x1,
        float* __restrict__ out)
{
    __shared__ uint32_t sx2[32 * 136];   // A: [kw][px] k-pair words
    __shared__ uint32_t ws[64 * 36];     // B: [o][kw]

    const int tid  = threadIdx.x;
    const int lane = tid & 31;
    const int warp = tid >> 5;
    const int r    = lane >> 2;
    const int c4   = lane & 3;
    const int p0   = blockIdx.x * 128;
    const int b    = p0 >> 16;
    const int hw0  = p0 & 65535;

    float acc[8][4];
#pragma unroll
    for (int nt = 0; nt < 8; nt++)
#pragma unroll
        for (int j = 0; j < 4; j++) acc[nt][j] = 0.f;

    const int px2 = tid & 63;
    const int kh  = tid >> 6;
    const bf16* yp = y + (size_t)(b * HID) * HW + hw0 + px2 * 2;

    for (int kc = 0; kc < 192; kc += 64) {
        __syncthreads();
#pragma unroll
        for (int j = 0; j < 8; j++) {
            const int kw = kh * 8 + j;
            const int k0 = kc + 2 * kw;
            uint32_t u0 = 0u, u1 = 0u;
            if (k0     < HID) u0 = *(const uint32_t*)(yp + (size_t)k0 * HW);
            if (k0 + 1 < HID) u1 = *(const uint32_t*)(yp + (size_t)(k0 + 1) * HW);
            const uint32_t v0 = (u0 & 0xffffu) | (u1 << 16);
            const uint32_t v1 = (u0 >> 16)     | (u1 & 0xffff0000u);
            uint64_t pair = (uint64_t)v0 | ((uint64_t)v1 << 32);
            *(uint64_t*)(sx2 + kw * 136 + px2 * 2) = pair;
        }
        for (int idx = tid; idx < 2048; idx += 256) {
            const int o = idx >> 5, kw = idx & 31;
            ws[o * 36 + kw] = wob[o * 96 + (kc >> 1) + kw];
        }
        __syncthreads();

#pragma unroll
        for (int kk = 0; kk < 4; kk++) {
            const int kb = kk * 8 + c4;
            const uint32_t a0 = sx2[kb * 136 + warp * 16 + r];
            const uint32_t a1 = sx2[kb * 136 + warp * 16 + r + 8];
            const uint32_t a2 = sx2[(kb + 4) * 136 + warp * 16 + r];
            const uint32_t a3 = sx2[(kb + 4) * 136 + warp * 16 + r + 8];
#pragma unroll
            for (int nt = 0; nt < 8; nt++) {
                const uint32_t b0 = ws[(nt * 8 + r) * 36 + kb];
                const uint32_t b1 = ws[(nt * 8 + r) * 36 + kb + 4];
                mma_bf16(acc[nt], a0, a1, a2, a3, b0, b1);
            }
        }
    }

    const int pixb = hw0 + warp * 16 + r;
#pragma unroll
    for (int nt = 0; nt < 8; nt++) {
        const int o = nt * 8 + 2 * c4;
        const size_t g = (size_t)(b * 64 + o) * HW + pixb;
        out[g]          = x1[g]          + acc[nt][0];
        out[g + HW]     = x1[g + HW]     + acc[nt][1];
        out[g + 8]      = x1[g + 8]      + acc[nt][2];
        out[g + HW + 8] = x1[g + HW + 8] + acc[nt][3];
    }
}

// ---------------- K2/K4: depthwise 3x3, bf16, 8-wide, halo via shfl -----------
// warp == one full 256-px image row (lane l covers pixels [8l, 8l+8)).
// Halo pixels come from neighbor lanes via shfl; lane 0/31 are true borders.
__device__ __forceinline__ void dw8w(const bf16* __restrict__ ip, int h, int lane,
                                     const float* wk, float* acc)
{
#pragma unroll
    for (int kh = 0; kh < 3; kh++) {
        const int hh = h + kh - 1;
        if ((unsigned)hh >= 256u) continue;          // warp-uniform predicate
        const bf16* rp = ip + hh * Ww + lane * 8;
        float f[8];
        bf8_to_f(*(const uint4*)rp, f);
        float left  = __shfl_up_sync(0xffffffffu, f[7], 1);
        float right = __shfl_down_sync(0xffffffffu, f[0], 1);
        if (lane == 0)  left  = 0.f;
        if (lane == 31) right = 0.f;
        const float k0 = wk[kh * 3], k1 = wk[kh * 3 + 1], k2 = wk[kh * 3 + 2];
        acc[0] += k0 * left + k1 * f[0] + k2 * f[1];
#pragma unroll
        for (int j = 1; j < 7; j++)
            acc[j] += k0 * f[j - 1] + k1 * f[j] + k2 * f[j + 1];
        acc[7] += k0 * f[6] + k1 * f[7] + k2 * right;
    }
}

template<int CHAN>
__global__ void __launch_bounds__(256) k_dw8(const bf16* __restrict__ in,
        const float* __restrict__ wt, bf16* __restrict__ out)
{
    const int idx = blockIdx.x * 256 + threadIdx.x;
    const int hwo = idx & 8191;
    const int cb  = idx >> 13;
    const int ch  = cb % CHAN;
    const int h = hwo >> 5;
    const int lane = threadIdx.x & 31;
    float wk[9];
#pragma unroll
    for (int j = 0; j < 9; j++) wk[j] = __ldg(&wt[ch * 9 + j]);
    const bf16* ip = in + ((size_t)cb << 16);
    float acc[8] = {0,0,0,0,0,0,0,0};
    dw8w(ip, h, lane, wk, acc);
    *(uint4*)(out + (size_t)idx * 8) = f_to_bf8(acc);
}

__global__ void __launch_bounds__(256) k_dwgate8(const bf16* __restrict__ in,
        const float* __restrict__ wt, bf16* __restrict__ out)
{
    const int idx = blockIdx.x * 256 + threadIdx.x;
    const int hwo = idx & 8191;
    const int cb  = idx >> 13;
    const int ch  = cb % HID;
    const int b   = cb / HID;
    const int h = hwo >> 5;
    const int lane = threadIdx.x & 31;

    float w1[9], w2[9];
#pragma unroll
    for (int j = 0; j < 9; j++) w1[j] = __ldg(&wt[ch * 9 + j]);
#pragma unroll
    for (int j = 0; j < 9; j++) w2[j] = __ldg(&wt[(ch + HID) * 9 + j]);

    const bf16* ip1 = in + (size_t)(b * C2 + ch) * HW;
    const bf16* ip2 = ip1 + (size_t)HID * HW;
    float a1[8] = {0,0,0,0,0,0,0,0}, a2[8] = {0,0,0,0,0,0,0,0};
    dw8w(ip1, h, lane, w1, a1);
    dw8w(ip2, h, lane, w2, a2);
    float o[8];
#pragma unroll
    for (int j = 0; j < 8; j++) {
        const float ge = 0.5f * a1[j] * (1.0f + erff(a1[j] * 0.70710678118654752f));
        o[j] = ge * a2[j];
    }
    *(uint4*)(out + (size_t)idx * 8) = f_to_bf8(o);
}

// ---------------- K3: window attention, bf16 MMA, 2 windows/block (frozen) ----
#define ATT_SMEM 55296
__global__ void __launch_bounds__(256, 4) k_attn_bf16(const bf16* __restrict__ qkv,
        const float* __restrict__ temp, const float* __restrict__ pw,
        const float* __restrict__ pb, const float* __restrict__ xres,
        float* __restrict__ xout)
{
    extern __shared__ char smem[];
    uint32_t* sq = (uint32_t*)smem;
    uint32_t* sk = (uint32_t*)(smem + 18432);
    uint32_t* sv = (uint32_t*)(smem + 36864);

    const int tid  = threadIdx.x;
    const int lane = tid & 31;
    const int w    = tid >> 5;
    const int r    = lane >> 2;
    const int c4   = lane & 3;

    const int blk  = blockIdx.x;
    const int b    = blk >> 9;
    const int row0 = ((blk >> 4) & 31) * 8;
    const int col0 = (blk & 15) * 16;

    for (int i = tid; i < 2048; i += 256) {
        const int hv = i & 1, row = (i >> 1) & 7, ch = (i >> 4) & 63, s = i >> 10;
        const bf16* src = qkv + ((size_t)(b * C3 + s * 64 + ch) << 16)
                        + (row0 + row) * Ww + col0 + hv * 8;
        uint4 u = *(const uint4*)src;
        uint32_t* dst = ((s == 0) ? sq : sk) + (hv * 64 + ch) * 36 + row * 4;
        *(uint4*)dst = u;
    }
    for (int i = tid; i < 1024; i += 256) {
        const int hv = i & 1, row = (i >> 1) & 7, ch = (i >> 4) & 63;
        const bf16* src = qkv + ((size_t)(b * C3 + 128 + ch) << 16)
                        + (row0 + row) * Ww + col0 + hv * 8;
        uint4 u = *(const uint4*)src;
        *(uint4*)(sv + (hv * 64 + ch) * 36 + row * 4) = u;
    }
    __syncthreads();

#pragma unroll
    for (int it = 0; it < 2; it++) {
        const int idx = tid + it * 256;
        const int rown = idx >> 1, hw2 = idx & 1;
        uint32_t* base = ((rown < 128) ? sq : sk) + (rown & 127) * 36 + hw2 * 16;
        float v[32]; float ss = 0.f;
#pragma unroll
        for (int j = 0; j < 4; j++) {
            uint4 u = *(uint4*)(base + j * 4);
            bf8_to_f(u, v + j * 8);
        }
#pragma unroll
        for (int j = 0; j < 32; j++) ss += v[j] * v[j];
        ss += __shfl_xor_sync(0xffffffffu, ss, 1);
        float sc = 1.f / fmaxf(sqrtf(ss), 1e-12f);
        if (rown < 128) sc *= __ldg(&temp[(rown >> 5) & 1]);
#pragma unroll
        for (int j = 0; j < 4; j++) {
            float t2[8];
#pragma unroll
            for (int m = 0; m < 8; m++) t2[m] = v[j * 8 + m] * sc;
            *(uint4*)(base + j * 4) = f_to_bf8(t2);
        }
    }
    __syncthreads();

    const int win = w >> 2, h = (w >> 1) & 1, mh = w & 1;

    float acc1[4][4];
#pragma unroll
    for (int nt = 0; nt < 4; nt++)
#pragma unroll
        for (int j = 0; j < 4; j++) acc1[nt][j] = 0.f;
    {
        const uint32_t* qb = sq + (win * 64 + h * 32 + mh * 16) * 36;
        const uint32_t* kb = sk + (win * 64 + h * 32) * 36;
#pragma unroll
        for (int kk = 0; kk < 4; kk++) {
            const int ko = kk * 8 + c4;
            const uint32_t a0 = qb[r * 36 + ko];
            const uint32_t a1 = qb[(r + 8) * 36 + ko];
            const uint32_t a2 = qb[r * 36 + ko + 4];
            const uint32_t a3 = qb[(r + 8) * 36 + ko + 4];
#pragma unroll
            for (int nt = 0; nt < 4; nt++) {
                const uint32_t b0 = kb[(nt * 8 + r) * 36 + ko];
                const uint32_t b1 = kb[(nt * 8 + r) * 36 + ko + 4];
                mma_bf16(acc1[nt], a0, a1, a2, a3, b0, b1);
            }
        }
    }

    uint32_t battn[2][4];
    {
        float m1 = -1e30f, m2 = -1e30f;
#pragma unroll
        for (int nt = 0; nt < 4; nt++) {
            m1 = fmaxf(m1, fmaxf(acc1[nt][0], acc1[nt][1]));
            m2 = fmaxf(m2, fmaxf(acc1[nt][2], acc1[nt][3]));
        }
        m1 = fmaxf(m1, __shfl_xor_sync(0xffffffffu, m1, 1));
        m1 = fmaxf(m1, __shfl_xor_sync(0xffffffffu, m1, 2));
        m2 = fmaxf(m2, __shfl_xor_sync(0xffffffffu, m2, 1));
        m2 = fmaxf(m2, __shfl_xor_sync(0xffffffffu, m2, 2));
        float s1 = 0.f, s2 = 0.f;
#pragma unroll
        for (int nt = 0; nt < 4; nt++) {
            acc1[nt][0] = __expf(acc1[nt][0] - m1);
            acc1[nt][1] = __expf(acc1[nt][1] - m1);
            acc1[nt][2] = __expf(acc1[nt][2] - m2);
            acc1[nt][3] = __expf(acc1[nt][3] - m2);
            s1 += acc1[nt][0] + acc1[nt][1];
            s2 += acc1[nt][2] + acc1[nt][3];
        }
        s1 += __shfl_xor_sync(0xffffffffu, s1, 1);
        s1 += __shfl_xor_sync(0xffffffffu, s1, 2);
        s2 += __shfl_xor_sync(0xffffffffu, s2, 1);
        s2 += __shfl_xor_sync(0xffffffffu, s2, 2);
        const float i1 = 1.f / s1, i2 = 1.f / s2;
        battn[0][0] = packbf(acc1[0][0] * i1, acc1[0][1] * i1);
        battn[0][1] = packbf(acc1[1][0] * i1, acc1[1][1] * i1);
        battn[0][2] = packbf(acc1[0][2] * i2, acc1[0][3] * i2);
        battn[0][3] = packbf(acc1[1][2] * i2, acc1[1][3] * i2);
        battn[1][0] = packbf(acc1[2][0] * i1, acc1[2][1] * i1);
        battn[1][1] = packbf(acc1[3][0] * i1, acc1[3][1] * i1);
        battn[1][2] = packbf(acc1[2][2] * i2, acc1[2][3] * i2);
        battn[1][3] = packbf(acc1[3][2] * i2, acc1[3][3] * i2);
    }
    __syncthreads();

    {
        const uint32_t svb = (uint32_t)__cvta_generic_to_shared(sv)
                           + (uint32_t)((win * 64 + h * 32) * 144);
        const int erow = ((lane >> 4) & 1) * 8 + (lane & 7);
        const int dcol = ((lane >> 3) & 1) * 8;
#pragma unroll
        for (int mt = 0; mt < 4; mt++) {
            float a2c[2][4];
#pragma unroll
            for (int nt = 0; nt < 2; nt++)
#pragma unroll
                for (int j = 0; j < 4; j++) a2c[nt][j] = 0.f;
#pragma unroll
            for (int kk2 = 0; kk2 < 2; kk2++) {
                uint32_t av[4];
                ldmx4t(av, svb + (uint32_t)((kk2 * 16 + erow) * 144
                                            + (mt * 16 + dcol) * 2));
                mma_bf16(a2c[0], av[0], av[1], av[2], av[3], battn[kk2][0], battn[kk2][1]);
                mma_bf16(a2c[1], av[0], av[1], av[2], av[3], battn[kk2][2], battn[kk2][3]);
            }
            const int base0 = (win * 64 + mt * 16 + r) * 36 + h * 16 + mh * 8 + c4;
            sq[base0]              = packbf(a2c[0][0], a2c[0][1]);
            sq[base0 + 4]          = packbf(a2c[1][0], a2c[1][1]);
            sq[base0 + 8 * 36]     = packbf(a2c[0][2], a2c[0][3]);
            sq[base0 + 8 * 36 + 4] = packbf(a2c[1][2], a2c[1][3]);
        }
    }

    for (int idx = tid; idx < 2048; idx += 256) {
        const int o = idx >> 5, cw = idx & 31;
        sk[o * 36 + cw] = packbf(pw[o * 64 + cw * 2], pw[o * 64 + cw * 2 + 1]);
    }
    __syncthreads();

    {
        const int oq = w & 3;
        const uint32_t* wpb = sk + (oq * 16) * 36;
        const uint32_t* ab  = sq + (win * 64) * 36;
        uint32_t a3r[4][4];
#pragma unroll
        for (int kk = 0; kk < 4; kk++) {
            const int ko = kk * 8 + c4;
            a3r[kk][0] = wpb[r * 36 + ko];
            a3r[kk][1] = wpb[(r + 8) * 36 + ko];
            a3r[kk][2] = wpb[r * 36 + ko + 4];
            a3r[kk][3] = wpb[(r + 8) * 36 + ko + 4];
        }
        const int o1 = oq * 16 + r, o2 = o1 + 8;
        const float bv1 = __ldg(&pb[o1]), bv2 = __ldg(&pb[o2]);
        const int pcol = col0 + win * 8 + 2 * c4;
#pragma unroll
        for (int nt = 0; nt < 8; nt++) {
            float c[4] = {0.f, 0.f, 0.f, 0.f};
#pragma unroll
            for (int kk = 0; kk < 4; kk++) {
                const int ko = kk * 8 + c4;
                const uint32_t b0 = ab[(nt * 8 + r) * 36 + ko];
                const uint32_t b1 = ab[(nt * 8 + r) * 36 + ko + 4];
                mma_bf16(c, a3r[kk][0], a3r[kk][1], a3r[kk][2], a3r[kk][3], b0, b1);
            }
            const size_t g1 = ((size_t)(b * Cc + o1) << 16) + (row0 + nt) * Ww + pcol;
            const size_t g2 = ((size_t)(b * Cc + o2) << 16) + (row0 + nt) * Ww + pcol;
            float2 x1v = *(const float2*)(xres + g1);
            float2 x2v = *(const float2*)(xres + g2);
            *(float2*)(xout + g1) = make_float2(x1v.x + c[0] + bv1, x1v.y + c[1] + bv1);
            *(float2*)(xout + g2) = make_float2(x2v.x + c[2] + bv2, x2v.y + c[3] + bv2);
        }
    }
}

// ---------------- launcher ----------------------------------------------------
extern "C" void kernel_launch(void* const* d_in, const int* in_sizes, int n_in,
                              void* d_out, int out_size)
{
    const float* x     = (const float*)d_in[0];
    const float* ln1w  = (const float*)d_in[1];
    const float* ln1b  = (const float*)d_in[2];
    const float* qkvw  = (const float*)d_in[3];
    const float* qkvdw = (const float*)d_in[4];
    const float* temp  = (const float*)d_in[5];
    const float* projw = (const float*)d_in[6];
    const float* projb = (const float*)d_in[7];
    const float* ln2w  = (const float*)d_in[8];
    const float* ln2b  = (const float*)d_in[9];
    const float* pinw  = (const float*)d_in[10];
    const float* dww   = (const float*)d_in[11];
    const float* poutw = (const float*)d_in[12];
    float* out = (float*)d_out;

    bf16 *qkv, *qkv2, *mid, *y;
    float *x1;
    uint32_t *wqb, *wpb, *wob;
    cudaGetSymbolAddress((void**)&qkv,  g_qkv);
    cudaGetSymbolAddress((void**)&qkv2, g_qkv2);
    cudaGetSymbolAddress((void**)&x1,   g_x1);
    cudaGetSymbolAddress((void**)&mid,  g_mid);
    cudaGetSymbolAddress((void**)&y,    g_y);
    cudaGetSymbolAddress((void**)&wqb,  g_wqb);
    cudaGetSymbolAddress((void**)&wpb,  g_wpb);
    cudaGetSymbolAddress((void**)&wob,  g_wob);

    cudaFuncSetAttribute(k_attn_bf16,
        cudaFuncAttributeMaxDynamicSharedMemorySize, ATT_SMEM);

    k_prep<<<48, 256>>>(qkvw, pinw, poutw, wqb, wpb, wob);
    // LN1 + qkv 1x1 -> qkv
    k_ln_bf16<C3><<<(Bz * HW) / 128, 256>>>(x, ln1w, ln1b, wqb, qkv);
    // depthwise 3x3 on qkv (halo via shfl)
    k_dw8<C3><<<(Bz * C3 * HW / 8) / 256, 256>>>(qkv, qkvdw, qkv2);
    // attention + proj + residual -> x1
    k_attn_bf16<<<Bz * 32 * 16, 256, ATT_SMEM>>>(qkv2, temp, projw, projb, x, x1);
    // LN2 + pin 1x1 -> mid
    k_ln_bf16<C2><<<(Bz * HW) / 128, 256>>>(x1, ln2w, ln2b, wpb, mid);
    // dwgate + GELU -> y (halo via shfl)
    k_dwgate8<<<(Bz * HID * HW / 8) / 256, 256>>>(mid, dww, y);
    // pout + residual -> out
    k_pout_bf16<<<(Bz * HW) / 128, 256>>>(y, wob, x1, out);
}

// round 15
// speedup vs baseline: 1.0393x; 1.0393x over previous
#include <cuda_runtime.h>
#include <cuda_bf16.h>
#include <math.h>
#include <stdint.h>

typedef __nv_bfloat16 bf16;

// Problem constants
#define Bz   4
#define Cc   64
#define Hh   256
#define Ww   256
#define HW   65536
#define HEADS 2
#define CH   32
#define WS   8
#define HID  170
#define C2   340
#define C3   192

// ---------------- scratch (device globals) ----------------
static __device__ bf16  g_qkv [(size_t)Bz*C3*HW];
static __device__ bf16  g_qkv2[(size_t)Bz*C3*HW];
static __device__ float g_x1  [(size_t)Bz*Cc*HW];       // residual carrier: fp32
static __device__ bf16  g_mid [(size_t)Bz*C2*HW];
static __device__ bf16  g_y   [(size_t)Bz*HID*HW];
// pre-packed bf16 weights, [o][k] pairs (uint32 = 2 k-consecutive bf16)
static __device__ uint32_t g_wqb[192 * 32];
static __device__ uint32_t g_wpb[384 * 32];
static __device__ uint32_t g_wob[64 * 96];

// ---------------- helpers ----------------
__device__ __forceinline__ void mma_bf16(float* c,
        uint32_t a0, uint32_t a1, uint32_t a2, uint32_t a3,
        uint32_t b0, uint32_t b1)
{
    asm volatile("mma.sync.aligned.m16n8k16.row.col.f32.bf16.bf16.f32 "
        "{%0,%1,%2,%3}, {%4,%5,%6,%7}, {%8,%9}, {%0,%1,%2,%3};"
        : "+f"(c[0]), "+f"(c[1]), "+f"(c[2]), "+f"(c[3])
        : "r"(a0), "r"(a1), "r"(a2), "r"(a3), "r"(b0), "r"(b1));
}

__device__ __forceinline__ void ldmx4t(uint32_t* a, uint32_t saddr) {
    asm volatile("ldmatrix.sync.aligned.m8n8.x4.trans.shared.b16 {%0,%1,%2,%3}, [%4];"
        : "=r"(a[0]), "=r"(a[1]), "=r"(a[2]), "=r"(a[3]) : "r"(saddr));
}

__device__ __forceinline__ uint32_t packbf(float x, float y) {
    __nv_bfloat162 t = __float22bfloat162_rn(make_float2(x, y));
    return *reinterpret_cast<uint32_t*>(&t);
}

__device__ __forceinline__ void bf8_to_f(const uint4& u, float* f) {
    float2 t;
    t = __bfloat1622float2(*reinterpret_cast<const __nv_bfloat162*>(&u.x)); f[0]=t.x; f[1]=t.y;
    t = __bfloat1622float2(*reinterpret_cast<const __nv_bfloat162*>(&u.y)); f[2]=t.x; f[3]=t.y;
    t = __bfloat1622float2(*reinterpret_cast<const __nv_bfloat162*>(&u.z)); f[4]=t.x; f[5]=t.y;
    t = __bfloat1622float2(*reinterpret_cast<const __nv_bfloat162*>(&u.w)); f[6]=t.x; f[7]=t.y;
}
__device__ __forceinline__ uint4 f_to_bf8(const float* f) {
    uint4 u;
    *reinterpret_cast<__nv_bfloat162*>(&u.x) = __float22bfloat162_rn(make_float2(f[0], f[1]));
    *reinterpret_cast<__nv_bfloat162*>(&u.y) = __float22bfloat162_rn(make_float2(f[2], f[3]));
    *reinterpret_cast<__nv_bfloat162*>(&u.z) = __float22bfloat162_rn(make_float2(f[4], f[5]));
    *reinterpret_cast<__nv_bfloat162*>(&u.w) = __float22bfloat162_rn(make_float2(f[6], f[7]));
    return u;
}

// ---------------- K0: weight prep (pack bf16 [o][k]) --------------------------
__global__ void __launch_bounds__(256) k_prep(const float* __restrict__ qkvw,
        const float* __restrict__ pinw, const float* __restrict__ poutw,
        uint32_t* __restrict__ wqb, uint32_t* __restrict__ wpb,
        uint32_t* __restrict__ wob)
{
    const int t = blockIdx.x * 256 + threadIdx.x;
    if (t < 192 * 32) {
        const int o = t >> 5, kw = t & 31;
        wqb[t] = packbf(qkvw[o * 64 + 2 * kw], qkvw[o * 64 + 2 * kw + 1]);
    }
    if (t < 384 * 32) {
        const int o = t >> 5, kw = t & 31;
        wpb[t] = (o < C2) ? packbf(pinw[o * 64 + 2 * kw], pinw[o * 64 + 2 * kw + 1]) : 0u;
    }
    if (t < 64 * 96) {
        const int o = t / 96, kw = t % 96;
        const int k0 = 2 * kw;
        const float v0 = (k0     < HID) ? poutw[o * HID + k0]     : 0.f;
        const float v1 = (k0 + 1 < HID) ? poutw[o * HID + k0 + 1] : 0.f;
        wob[t] = packbf(v0, v1);
    }
}

// ---------------- K1/K3: fused LayerNorm + 1x1 conv, bf16 MMA -----------------
template<int COUT>
__global__ void __launch_bounds__(256) k_ln_bf16(const float* __restrict__ xin,
        const float* __restrict__ gw, const float* __restrict__ gb,
        const uint32_t* __restrict__ wb, bf16* __restrict__ out)
{
    __shared__ uint32_t sx[128 * 36];
    __shared__ uint32_t ws[64 * 36];

    const int tid  = threadIdx.x;
    const int lane = tid & 31;
    const int warp = tid >> 5;
    const int r    = lane >> 2;
    const int c4   = lane & 3;
    const int p0   = blockIdx.x * 128;
    const int b    = p0 >> 16;
    const int hw0  = p0 & 65535;

    {
        const int pl = tid >> 1, half = tid & 1;
        const float* xp = xin + (size_t)(b * 64 + half * 32) * HW + hw0 + pl;
        float xv[32];
        float s = 0.f, s2 = 0.f;
#pragma unroll
        for (int i = 0; i < 32; i++) {
            xv[i] = xp[(size_t)i * HW];
            s += xv[i]; s2 += xv[i] * xv[i];
        }
        s  += __shfl_xor_sync(0xffffffffu, s, 1);
        s2 += __shfl_xor_sync(0xffffffffu, s2, 1);
        const float mu   = s * (1.f / 64.f);
        const float var  = fmaxf(s2 * (1.f / 64.f) - mu * mu, 0.f);
        const float rstd = rsqrtf(var + 1e-5f);
        uint32_t* sxp = sx + pl * 36 + half * 16;
#pragma unroll
        for (int i2 = 0; i2 < 16; i2++) {
            const int c = half * 32 + 2 * i2;
            const float v0 = (xv[2*i2]   - mu) * rstd * __ldg(&gw[c])   + __ldg(&gb[c]);
            const float v1 = (xv[2*i2+1] - mu) * rstd * __ldg(&gw[c+1]) + __ldg(&gb[c+1]);
            sxp[i2] = packbf(v0, v1);
        }
    }
    __syncthreads();

    const uint32_t* ap = sx + (warp * 16 + r) * 36 + c4;
    uint32_t areg[4][4];
#pragma unroll
    for (int kk = 0; kk < 4; kk++) {
        const int kb = kk * 8;
        areg[kk][0] = ap[kb];
        areg[kk][1] = ap[8 * 36 + kb];
        areg[kk][2] = ap[kb + 4];
        areg[kk][3] = ap[8 * 36 + kb + 4];
    }

    const int pixb = hw0 + warp * 16 + r;
    const bool evenr = (r & 1) == 0;
    const int NCH  = (COUT + 63) / 64;
    for (int chunk = 0; chunk < NCH; chunk++) {
        const int och = chunk * 64;
        __syncthreads();
        for (int idx = tid; idx < 2048; idx += 256) {
            const int o = idx >> 5, kw = idx & 31;
            ws[o * 36 + kw] = wb[(och + o) * 32 + kw];
        }
        __syncthreads();

        float acc[8][4];
#pragma unroll
        for (int nt = 0; nt < 8; nt++)
#pragma unroll
            for (int j = 0; j < 4; j++) acc[nt][j] = 0.f;

#pragma unroll
        for (int kk = 0; kk < 4; kk++) {
            const int kb = kk * 8 + c4;
#pragma unroll
            for (int nt = 0; nt < 8; nt++) {
                const uint32_t b0 = ws[(nt * 8 + r) * 36 + kb];
                const uint32_t b1 = ws[(nt * 8 + r) * 36 + kb + 4];
                mma_bf16(acc[nt], areg[kk][0], areg[kk][1], areg[kk][2], areg[kk][3],
                         b0, b1);
            }
        }

        // ---- packed store epilogue: shfl pixel-pair exchange -> STG.32
#pragma unroll
        for (int nt = 0; nt < 8; nt++) {
            const int o = och + nt * 8 + 2 * c4;
            const float pc0 = __shfl_xor_sync(0xffffffffu, acc[nt][0], 4);
            const float pc1 = __shfl_xor_sync(0xffffffffu, acc[nt][1], 4);
            const float pc2 = __shfl_xor_sync(0xffffffffu, acc[nt][2], 4);
            const float pc3 = __shfl_xor_sync(0xffffffffu, acc[nt][3], 4);
            if (evenr) {
                if ((COUT & 63) == 0 || o < COUT) {
                    uint32_t* p = (uint32_t*)(out + (size_t)(b * COUT + o) * HW + pixb);
                    p[0] = packbf(acc[nt][0], pc0);
                    p[4] = packbf(acc[nt][2], pc2);
                }
            } else {
                if ((COUT & 63) == 0 || o + 1 < COUT) {
                    uint32_t* p = (uint32_t*)(out + (size_t)(b * COUT + o + 1) * HW + pixb - 1);
                    p[0] = packbf(pc1, acc[nt][1]);
                    p[4] = packbf(pc3, acc[nt][3]);
                }
            }
        }
    }
}

// ---------------- K5: pout (64 x 170) bf16 MMA + residual ----------------------
__global__ void __launch_bounds__(256) k_pout_bf16(const bf16* __restrict__ y,
        const uint32_t* __restrict__ wob, const float* __restrict__ x1,
        float* __restrict__ out)
{
    __shared__ uint32_t sx2[32 * 136];   // A: [kw][px] k-pair words
    __shared__ uint32_t ws[64 * 36];     // B: [o][kw]

    const int tid  = threadIdx.x;
    const int lane = tid & 31;
    const int warp = tid >> 5;
    const int r    = lane >> 2;
    const int c4   = lane & 3;
    const int p0   = blockIdx.x * 128;
    const int b    = p0 >> 16;
    const int hw0  = p0 & 65535;

    float acc[8][4];
#pragma unroll
    for (int nt = 0; nt < 8; nt++)
#pragma unroll
        for (int j = 0; j < 4; j++) acc[nt][j] = 0.f;

    const int px2 = tid & 63;
    const int kh  = tid >> 6;
    const bf16* yp = y + (size_t)(b * HID) * HW + hw0 + px2 * 2;

    for (int kc = 0; kc < 192; kc += 64) {
        __syncthreads();
#pragma unroll
        for (int j = 0; j < 8; j++) {
            const int kw = kh * 8 + j;
            const int k0 = kc + 2 * kw;
            uint32_t u0 = 0u, u1 = 0u;
            if (k0     < HID) u0 = *(const uint32_t*)(yp + (size_t)k0 * HW);
            if (k0 + 1 < HID) u1 = *(const uint32_t*)(yp + (size_t)(k0 + 1) * HW);
            const uint32_t v0 = (u0 & 0xffffu) | (u1 << 16);
            const uint32_t v1 = (u0 >> 16)     | (u1 & 0xffff0000u);
            uint64_t pair = (uint64_t)v0 | ((uint64_t)v1 << 32);
            *(uint64_t*)(sx2 + kw * 136 + px2 * 2) = pair;
        }
        for (int idx = tid; idx < 2048; idx += 256) {
            const int o = idx >> 5, kw = idx & 31;
            ws[o * 36 + kw] = wob[o * 96 + (kc >> 1) + kw];
        }
        __syncthreads();

#pragma unroll
        for (int kk = 0; kk < 4; kk++) {
            const int kb = kk * 8 + c4;
            const uint32_t a0 = sx2[kb * 136 + warp * 16 + r];
            const uint32_t a1 = sx2[kb * 136 + warp * 16 + r + 8];
            const uint32_t a2 = sx2[(kb + 4) * 136 + warp * 16 + r];
            const uint32_t a3 = sx2[(kb + 4) * 136 + warp * 16 + r + 8];
#pragma unroll
            for (int nt = 0; nt < 8; nt++) {
                const uint32_t b0 = ws[(nt * 8 + r) * 36 + kb];
                const uint32_t b1 = ws[(nt * 8 + r) * 36 + kb + 4];
                mma_bf16(acc[nt], a0, a1, a2, a3, b0, b1);
            }
        }
    }

    const int pixb = hw0 + warp * 16 + r;
#pragma unroll
    for (int nt = 0; nt < 8; nt++) {
        const int o = nt * 8 + 2 * c4;
        const size_t g = (size_t)(b * 64 + o) * HW + pixb;
        out[g]          = x1[g]          + acc[nt][0];
        out[g + HW]     = x1[g + HW]     + acc[nt][1];
        out[g + 8]      = x1[g + 8]      + acc[nt][2];
        out[g + HW + 8] = x1[g + HW + 8] + acc[nt][3];
    }
}

// ---------------- K2/K4: depthwise 3x3, bf16, 8px x 2 rows per thread ---------
// 2 output rows share 4 input rows (vertical reuse): -33% loads, MLP up.
template<int CHAN>
__global__ void __launch_bounds__(256) k_dw8(const bf16* __restrict__ in,
        const float* __restrict__ wt, bf16* __restrict__ out)
{
    const int idx = blockIdx.x * 256 + threadIdx.x;      // over B*CHAN*HW/16
    const int hwo = idx & 4095;
    const int cb  = idx >> 12;
    const int ch  = cb % CHAN;
    const int h0  = (hwo >> 5) * 2;
    const int w0  = (hwo & 31) * 8;
    float wk[9];
#pragma unroll
    for (int j = 0; j < 9; j++) wk[j] = __ldg(&wt[ch * 9 + j]);
    const bf16* ip = in + ((size_t)cb << 16);

    float acc[2][8];
#pragma unroll
    for (int q = 0; q < 2; q++)
#pragma unroll
        for (int j = 0; j < 8; j++) acc[q][j] = 0.f;

#pragma unroll
    for (int kr = 0; kr < 4; kr++) {
        const int rr = h0 - 1 + kr;
        if ((unsigned)rr >= 256u) continue;
        const bf16* rp = ip + rr * Ww + w0;
        float rv[10];
        rv[0] = (w0 > 0)   ? __bfloat162float(rp[-1]) : 0.f;
        rv[9] = (w0 < 248) ? __bfloat162float(rp[8])  : 0.f;
        bf8_to_f(*(const uint4*)rp, rv + 1);
        if (kr <= 2) {
            const float k0 = wk[kr*3], k1 = wk[kr*3+1], k2 = wk[kr*3+2];
#pragma unroll
            for (int j = 0; j < 8; j++)
                acc[0][j] += k0 * rv[j] + k1 * rv[j + 1] + k2 * rv[j + 2];
        }
        if (kr >= 1) {
            const float k0 = wk[(kr-1)*3], k1 = wk[(kr-1)*3+1], k2 = wk[(kr-1)*3+2];
#pragma unroll
            for (int j = 0; j < 8; j++)
                acc[1][j] += k0 * rv[j] + k1 * rv[j + 1] + k2 * rv[j + 2];
        }
    }
    bf16* op = out + ((size_t)cb << 16) + h0 * Ww + w0;
    *(uint4*)op        = f_to_bf8(acc[0]);
    *(uint4*)(op + Ww) = f_to_bf8(acc[1]);
}

__global__ void __launch_bounds__(256) k_dwgate8(const bf16* __restrict__ in,
        const float* __restrict__ wt, bf16* __restrict__ out)
{
    const int idx = blockIdx.x * 256 + threadIdx.x;      // over B*HID*HW/16
    const int hwo = idx & 4095;
    const int cb  = idx >> 12;
    const int ch  = cb % HID;
    const int b   = cb / HID;
    const int h0  = (hwo >> 5) * 2;
    const int w0  = (hwo & 31) * 8;

    const bf16* ip1 = in + (size_t)(b * C2 + ch) * HW;
    const bf16* ip2 = ip1 + (size_t)HID * HW;

    float a1[2][8], a2[2][8];
#pragma unroll
    for (int q = 0; q < 2; q++)
#pragma unroll
        for (int j = 0; j < 8; j++) { a1[q][j] = 0.f; a2[q][j] = 0.f; }

    {
        float w1[9];
#pragma unroll
        for (int j = 0; j < 9; j++) w1[j] = __ldg(&wt[ch * 9 + j]);
#pragma unroll
        for (int kr = 0; kr < 4; kr++) {
            const int rr = h0 - 1 + kr;
            if ((unsigned)rr >= 256u) continue;
            const bf16* rp = ip1 + rr * Ww + w0;
            float rv[10];
            rv[0] = (w0 > 0)   ? __bfloat162float(rp[-1]) : 0.f;
            rv[9] = (w0 < 248) ? __bfloat162float(rp[8])  : 0.f;
            bf8_to_f(*(const uint4*)rp, rv + 1);
            if (kr <= 2) {
                const float k0 = w1[kr*3], k1 = w1[kr*3+1], k2 = w1[kr*3+2];
#pragma unroll
                for (int j = 0; j < 8; j++)
                    a1[0][j] += k0 * rv[j] + k1 * rv[j + 1] + k2 * rv[j + 2];
            }
            if (kr >= 1) {
                const float k0 = w1[(kr-1)*3], k1 = w1[(kr-1)*3+1], k2 = w1[(kr-1)*3+2];
#pragma unroll
                for (int j = 0; j < 8; j++)
                    a1[1][j] += k0 * rv[j] + k1 * rv[j + 1] + k2 * rv[j + 2];
            }
        }
    }
    {
        float w2[9];
#pragma unroll
        for (int j = 0; j < 9; j++) w2[j] = __ldg(&wt[(ch + HID) * 9 + j]);
#pragma unroll
        for (int kr = 0; kr < 4; kr++) {
            const int rr = h0 - 1 + kr;
            if ((unsigned)rr >= 256u) continue;
            const bf16* rp = ip2 + rr * Ww + w0;
            float rv[10];
            rv[0] = (w0 > 0)   ? __bfloat162float(rp[-1]) : 0.f;
            rv[9] = (w0 < 248) ? __bfloat162float(rp[8])  : 0.f;
            bf8_to_f(*(const uint4*)rp, rv + 1);
            if (kr <= 2) {
                const float k0 = w2[kr*3], k1 = w2[kr*3+1], k2 = w2[kr*3+2];
#pragma unroll
                for (int j = 0; j < 8; j++)
                    a2[0][j] += k0 * rv[j] + k1 * rv[j + 1] + k2 * rv[j + 2];
            }
            if (kr >= 1) {
                const float k0 = w2[(kr-1)*3], k1 = w2[(kr-1)*3+1], k2 = w2[(kr-1)*3+2];
#pragma unroll
                for (int j = 0; j < 8; j++)
                    a2[1][j] += k0 * rv[j] + k1 * rv[j + 1] + k2 * rv[j + 2];
            }
        }
    }

    bf16* op = out + (size_t)(b * HID + ch) * HW + h0 * Ww + w0;
#pragma unroll
    for (int q = 0; q < 2; q++) {
        float o[8];
#pragma unroll
        for (int j = 0; j < 8; j++) {
            const float ge = 0.5f * a1[q][j] * (1.0f + erff(a1[q][j] * 0.70710678118654752f));
            o[j] = ge * a2[q][j];
        }
        *(uint4*)(op + q * Ww) = f_to_bf8(o);
    }
}

// ---------------- K3: window attention, bf16 MMA, 2 windows/block (frozen) ----
#define ATT_SMEM 55296
__global__ void __launch_bounds__(256, 4) k_attn_bf16(const bf16* __restrict__ qkv,
        const float* __restrict__ temp, const float* __restrict__ pw,
        const float* __restrict__ pb, const float* __restrict__ xres,
        float* __restrict__ xout)
{
    extern __shared__ char smem[];
    uint32_t* sq = (uint32_t*)smem;
    uint32_t* sk = (uint32_t*)(smem + 18432);
    uint32_t* sv = (uint32_t*)(smem + 36864);

    const int tid  = threadIdx.x;
    const int lane = tid & 31;
    const int w    = tid >> 5;
    const int r    = lane >> 2;
    const int c4   = lane & 3;

    const int blk  = blockIdx.x;
    const int b    = blk >> 9;
    const int row0 = ((blk >> 4) & 31) * 8;
    const int col0 = (blk & 15) * 16;

    for (int i = tid; i < 2048; i += 256) {
        const int hv = i & 1, row = (i >> 1) & 7, ch = (i >> 4) & 63, s = i >> 10;
        const bf16* src = qkv + ((size_t)(b * C3 + s * 64 + ch) << 16)
                        + (row0 + row) * Ww + col0 + hv * 8;
        uint4 u = *(const uint4*)src;
        uint32_t* dst = ((s == 0) ? sq : sk) + (hv * 64 + ch) * 36 + row * 4;
        *(uint4*)dst = u;
    }
    for (int i = tid; i < 1024; i += 256) {
        const int hv = i & 1, row = (i >> 1) & 7, ch = (i >> 4) & 63;
        const bf16* src = qkv + ((size_t)(b * C3 + 128 + ch) << 16)
                        + (row0 + row) * Ww + col0 + hv * 8;
        uint4 u = *(const uint4*)src;
        *(uint4*)(sv + (hv * 64 + ch) * 36 + row * 4) = u;
    }
    __syncthreads();

#pragma unroll
    for (int it = 0; it < 2; it++) {
        const int idx = tid + it * 256;
        const int rown = idx >> 1, hw2 = idx & 1;
        uint32_t* base = ((rown < 128) ? sq : sk) + (rown & 127) * 36 + hw2 * 16;
        float v[32]; float ss = 0.f;
#pragma unroll
        for (int j = 0; j < 4; j++) {
            uint4 u = *(uint4*)(base + j * 4);
            bf8_to_f(u, v + j * 8);
        }
#pragma unroll
        for (int j = 0; j < 32; j++) ss += v[j] * v[j];
        ss += __shfl_xor_sync(0xffffffffu, ss, 1);
        float sc = 1.f / fmaxf(sqrtf(ss), 1e-12f);
        if (rown < 128) sc *= __ldg(&temp[(rown >> 5) & 1]);
#pragma unroll
        for (int j = 0; j < 4; j++) {
            float t2[8];
#pragma unroll
            for (int m = 0; m < 8; m++) t2[m] = v[j * 8 + m] * sc;
            *(uint4*)(base + j * 4) = f_to_bf8(t2);
        }
    }
    __syncthreads();

    const int win = w >> 2, h = (w >> 1) & 1, mh = w & 1;

    float acc1[4][4];
#pragma unroll
    for (int nt = 0; nt < 4; nt++)
#pragma unroll
        for (int j = 0; j < 4; j++) acc1[nt][j] = 0.f;
    {
        const uint32_t* qb = sq + (win * 64 + h * 32 + mh * 16) * 36;
        const uint32_t* kb = sk + (win * 64 + h * 32) * 36;
#pragma unroll
        for (int kk = 0; kk < 4; kk++) {
            const int ko = kk * 8 + c4;
            const uint32_t a0 = qb[r * 36 + ko];
            const uint32_t a1 = qb[(r + 8) * 36 + ko];
            const uint32_t a2 = qb[r * 36 + ko + 4];
            const uint32_t a3 = qb[(r + 8) * 36 + ko + 4];
#pragma unroll
            for (int nt = 0; nt < 4; nt++) {
                const uint32_t b0 = kb[(nt * 8 + r) * 36 + ko];
                const uint32_t b1 = kb[(nt * 8 + r) * 36 + ko + 4];
                mma_bf16(acc1[nt], a0, a1, a2, a3, b0, b1);
            }
        }
    }

    uint32_t battn[2][4];
    {
        float m1 = -1e30f, m2 = -1e30f;
#pragma unroll
        for (int nt = 0; nt < 4; nt++) {
            m1 = fmaxf(m1, fmaxf(acc1[nt][0], acc1[nt][1]));
            m2 = fmaxf(m2, fmaxf(acc1[nt][2], acc1[nt][3]));
        }
        m1 = fmaxf(m1, __shfl_xor_sync(0xffffffffu, m1, 1));
        m1 = fmaxf(m1, __shfl_xor_sync(0xffffffffu, m1, 2));
        m2 = fmaxf(m2, __shfl_xor_sync(0xffffffffu, m2, 1));
        m2 = fmaxf(m2, __shfl_xor_sync(0xffffffffu, m2, 2));
        float s1 = 0.f, s2 = 0.f;
#pragma unroll
        for (int nt = 0; nt < 4; nt++) {
            acc1[nt][0] = __expf(acc1[nt][0] - m1);
            acc1[nt][1] = __expf(acc1[nt][1] - m1);
            acc1[nt][2] = __expf(acc1[nt][2] - m2);
            acc1[nt][3] = __expf(acc1[nt][3] - m2);
            s1 += acc1[nt][0] + acc1[nt][1];
            s2 += acc1[nt][2] + acc1[nt][3];
        }
        s1 += __shfl_xor_sync(0xffffffffu, s1, 1);
        s1 += __shfl_xor_sync(0xffffffffu, s1, 2);
        s2 += __shfl_xor_sync(0xffffffffu, s2, 1);
        s2 += __shfl_xor_sync(0xffffffffu, s2, 2);
        const float i1 = 1.f / s1, i2 = 1.f / s2;
        battn[0][0] = packbf(acc1[0][0] * i1, acc1[0][1] * i1);
        battn[0][1] = packbf(acc1[1][0] * i1, acc1[1][1] * i1);
        battn[0][2] = packbf(acc1[0][2] * i2, acc1[0][3] * i2);
        battn[0][3] = packbf(acc1[1][2] * i2, acc1[1][3] * i2);
        battn[1][0] = packbf(acc1[2][0] * i1, acc1[2][1] * i1);
        battn[1][1] = packbf(acc1[3][0] * i1, acc1[3][1] * i1);
        battn[1][2] = packbf(acc1[2][2] * i2, acc1[2][3] * i2);
        battn[1][3] = packbf(acc1[3][2] * i2, acc1[3][3] * i2);
    }
    __syncthreads();

    {
        const uint32_t svb = (uint32_t)__cvta_generic_to_shared(sv)
                           + (uint32_t)((win * 64 + h * 32) * 144);
        const int erow = ((lane >> 4) & 1) * 8 + (lane & 7);
        const int dcol = ((lane >> 3) & 1) * 8;
#pragma unroll
        for (int mt = 0; mt < 4; mt++) {
            float a2c[2][4];
#pragma unroll
            for (int nt = 0; nt < 2; nt++)
#pragma unroll
                for (int j = 0; j < 4; j++) a2c[nt][j] = 0.f;
#pragma unroll
            for (int kk2 = 0; kk2 < 2; kk2++) {
                uint32_t av[4];
                ldmx4t(av, svb + (uint32_t)((kk2 * 16 + erow) * 144
                                            + (mt * 16 + dcol) * 2));
                mma_bf16(a2c[0], av[0], av[1], av[2], av[3], battn[kk2][0], battn[kk2][1]);
                mma_bf16(a2c[1], av[0], av[1], av[2], av[3], battn[kk2][2], battn[kk2][3]);
            }
            const int base0 = (win * 64 + mt * 16 + r) * 36 + h * 16 + mh * 8 + c4;
            sq[base0]              = packbf(a2c[0][0], a2c[0][1]);
            sq[base0 + 4]          = packbf(a2c[1][0], a2c[1][1]);
            sq[base0 + 8 * 36]     = packbf(a2c[0][2], a2c[0][3]);
            sq[base0 + 8 * 36 + 4] = packbf(a2c[1][2], a2c[1][3]);
        }
    }

    for (int idx = tid; idx < 2048; idx += 256) {
        const int o = idx >> 5, cw = idx & 31;
        sk[o * 36 + cw] = packbf(pw[o * 64 + cw * 2], pw[o * 64 + cw * 2 + 1]);
    }
    __syncthreads();

    {
        const int oq = w & 3;
        const uint32_t* wpb = sk + (oq * 16) * 36;
        const uint32_t* ab  = sq + (win * 64) * 36;
        uint32_t a3r[4][4];
#pragma unroll
        for (int kk = 0; kk < 4; kk++) {
            const int ko = kk * 8 + c4;
            a3r[kk][0] = wpb[r * 36 + ko];
            a3r[kk][1] = wpb[(r + 8) * 36 + ko];
            a3r[kk][2] = wpb[r * 36 + ko + 4];
            a3r[kk][3] = wpb[(r + 8) * 36 + ko + 4];
        }
        const int o1 = oq * 16 + r, o2 = o1 + 8;
        const float bv1 = __ldg(&pb[o1]), bv2 = __ldg(&pb[o2]);
        const int pcol = col0 + win * 8 + 2 * c4;
#pragma unroll
        for (int nt = 0; nt < 8; nt++) {
            float c[4] = {0.f, 0.f, 0.f, 0.f};
#pragma unroll
            for (int kk = 0; kk < 4; kk++) {
                const int ko = kk * 8 + c4;
                const uint32_t b0 = ab[(nt * 8 + r) * 36 + ko];
                const uint32_t b1 = ab[(nt * 8 + r) * 36 + ko + 4];
                mma_bf16(c, a3r[kk][0], a3r[kk][1], a3r[kk][2], a3r[kk][3], b0, b1);
            }
            const size_t g1 = ((size_t)(b * Cc + o1) << 16) + (row0 + nt) * Ww + pcol;
            const size_t g2 = ((size_t)(b * Cc + o2) << 16) + (row0 + nt) * Ww + pcol;
            float2 x1v = *(const float2*)(xres + g1);
            float2 x2v = *(const float2*)(xres + g2);
            *(float2*)(xout + g1) = make_float2(x1v.x + c[0] + bv1, x1v.y + c[1] + bv1);
            *(float2*)(xout + g2) = make_float2(x2v.x + c[2] + bv2, x2v.y + c[3] + bv2);
        }
    }
}

// ---------------- launcher ----------------------------------------------------
extern "C" void kernel_launch(void* const* d_in, const int* in_sizes, int n_in,
                              void* d_out, int out_size)
{
    const float* x     = (const float*)d_in[0];
    const float* ln1w  = (const float*)d_in[1];
    const float* ln1b  = (const float*)d_in[2];
    const float* qkvw  = (const float*)d_in[3];
    const float* qkvdw = (const float*)d_in[4];
    const float* temp  = (const float*)d_in[5];
    const float* projw = (const float*)d_in[6];
    const float* projb = (const float*)d_in[7];
    const float* ln2w  = (const float*)d_in[8];
    const float* ln2b  = (const float*)d_in[9];
    const float* pinw  = (const float*)d_in[10];
    const float* dww   = (const float*)d_in[11];
    const float* poutw = (const float*)d_in[12];
    float* out = (float*)d_out;

    bf16 *qkv, *qkv2, *mid, *y;
    float *x1;
    uint32_t *wqb, *wpb, *wob;
    cudaGetSymbolAddress((void**)&qkv,  g_qkv);
    cudaGetSymbolAddress((void**)&qkv2, g_qkv2);
    cudaGetSymbolAddress((void**)&x1,   g_x1);
    cudaGetSymbolAddress((void**)&mid,  g_mid);
    cudaGetSymbolAddress((void**)&y,    g_y);
    cudaGetSymbolAddress((void**)&wqb,  g_wqb);
    cudaGetSymbolAddress((void**)&wpb,  g_wpb);
    cudaGetSymbolAddress((void**)&wob,  g_wob);

    cudaFuncSetAttribute(k_attn_bf16,
        cudaFuncAttributeMaxDynamicSharedMemorySize, ATT_SMEM);

    k_prep<<<48, 256>>>(qkvw, pinw, poutw, wqb, wpb, wob);
    // LN1 + qkv 1x1 -> qkv
    k_ln_bf16<C3><<<(Bz * HW) / 128, 256>>>(x, ln1w, ln1b, wqb, qkv);
    // depthwise 3x3 on qkv (2 rows/thread)
    k_dw8<C3><<<(Bz * C3 * HW / 16) / 256, 256>>>(qkv, qkvdw, qkv2);
    // attention + proj + residual -> x1
    k_attn_bf16<<<Bz * 32 * 16, 256, ATT_SMEM>>>(qkv2, temp, projw, projb, x, x1);
    // LN2 + pin 1x1 -> mid
    k_ln_bf16<C2><<<(Bz * HW) / 128, 256>>>(x1, ln2w, ln2b, wpb, mid);
    // dwgate + GELU -> y (2 rows/thread)
    k_dwgate8<<<(Bz * HID * HW / 16) / 256, 256>>>(mid, dww, y);
    // pout + residual -> out
    k_pout_bf16<<<(Bz * HW) / 128, 256>>>(y, wob, x1, out);
}

// round 16
// speedup vs baseline: 1.0415x; 1.0021x over previous
#include <cuda_runtime.h>
#include <cuda_bf16.h>
#include <math.h>
#include <stdint.h>

typedef __nv_bfloat16 bf16;

// Problem constants
#define Bz   4
#define Cc   64
#define Hh   256
#define Ww   256
#define HW   65536
#define HEADS 2
#define CH   32
#define WS   8
#define HID  170
#define C2   340
#define C3   192

// ---------------- scratch (device globals) ----------------
static __device__ bf16  g_qkv [(size_t)Bz*C3*HW];
static __device__ bf16  g_qkv2[(size_t)Bz*C3*HW];
static __device__ float g_x1  [(size_t)Bz*Cc*HW];       // residual carrier: fp32
static __device__ bf16  g_mid [(size_t)Bz*C2*HW];
static __device__ bf16  g_y   [(size_t)Bz*HID*HW];
// pre-packed bf16 weights, [o][k] pairs (uint32 = 2 k-consecutive bf16)
static __device__ uint32_t g_wqb[192 * 32];
static __device__ uint32_t g_wpb[384 * 32];
static __device__ uint32_t g_wob[64 * 96];

// ---------------- helpers ----------------
__device__ __forceinline__ void mma_bf16(float* c,
        uint32_t a0, uint32_t a1, uint32_t a2, uint32_t a3,
        uint32_t b0, uint32_t b1)
{
    asm volatile("mma.sync.aligned.m16n8k16.row.col.f32.bf16.bf16.f32 "
        "{%0,%1,%2,%3}, {%4,%5,%6,%7}, {%8,%9}, {%0,%1,%2,%3};"
        : "+f"(c[0]), "+f"(c[1]), "+f"(c[2]), "+f"(c[3])
        : "r"(a0), "r"(a1), "r"(a2), "r"(a3), "r"(b0), "r"(b1));
}

__device__ __forceinline__ void ldmx4t(uint32_t* a, uint32_t saddr) {
    asm volatile("ldmatrix.sync.aligned.m8n8.x4.trans.shared.b16 {%0,%1,%2,%3}, [%4];"
        : "=r"(a[0]), "=r"(a[1]), "=r"(a[2]), "=r"(a[3]) : "r"(saddr));
}

__device__ __forceinline__ uint32_t packbf(float x, float y) {
    __nv_bfloat162 t = __float22bfloat162_rn(make_float2(x, y));
    return *reinterpret_cast<uint32_t*>(&t);
}

__device__ __forceinline__ void bf8_to_f(const uint4& u, float* f) {
    float2 t;
    t = __bfloat1622float2(*reinterpret_cast<const __nv_bfloat162*>(&u.x)); f[0]=t.x; f[1]=t.y;
    t = __bfloat1622float2(*reinterpret_cast<const __nv_bfloat162*>(&u.y)); f[2]=t.x; f[3]=t.y;
    t = __bfloat1622float2(*reinterpret_cast<const __nv_bfloat162*>(&u.z)); f[4]=t.x; f[5]=t.y;
    t = __bfloat1622float2(*reinterpret_cast<const __nv_bfloat162*>(&u.w)); f[6]=t.x; f[7]=t.y;
}
__device__ __forceinline__ uint4 f_to_bf8(const float* f) {
    uint4 u;
    *reinterpret_cast<__nv_bfloat162*>(&u.x) = __float22bfloat162_rn(make_float2(f[0], f[1]));
    *reinterpret_cast<__nv_bfloat162*>(&u.y) = __float22bfloat162_rn(make_float2(f[2], f[3]));
    *reinterpret_cast<__nv_bfloat162*>(&u.z) = __float22bfloat162_rn(make_float2(f[4], f[5]));
    *reinterpret_cast<__nv_bfloat162*>(&u.w) = __float22bfloat162_rn(make_float2(f[6], f[7]));
    return u;
}

// ---------------- K0: weight prep (pack bf16 [o][k]) --------------------------
__global__ void __launch_bounds__(256) k_prep(const float* __restrict__ qkvw,
        const float* __restrict__ pinw, const float* __restrict__ poutw,
        uint32_t* __restrict__ wqb, uint32_t* __restrict__ wpb,
        uint32_t* __restrict__ wob)
{
    const int t = blockIdx.x * 256 + threadIdx.x;
    if (t < 192 * 32) {
        const int o = t >> 5, kw = t & 31;
        wqb[t] = packbf(qkvw[o * 64 + 2 * kw], qkvw[o * 64 + 2 * kw + 1]);
    }
    if (t < 384 * 32) {
        const int o = t >> 5, kw = t & 31;
        wpb[t] = (o < C2) ? packbf(pinw[o * 64 + 2 * kw], pinw[o * 64 + 2 * kw + 1]) : 0u;
    }
    if (t < 64 * 96) {
        const int o = t / 96, kw = t % 96;
        const int k0 = 2 * kw;
        const float v0 = (k0     < HID) ? poutw[o * HID + k0]     : 0.f;
        const float v1 = (k0 + 1 < HID) ? poutw[o * HID + k0 + 1] : 0.f;
        wob[t] = packbf(v0, v1);
    }
}

// ---------------- K1/K3: fused LayerNorm + 1x1 conv, bf16 MMA, dbl-buffered ---
template<int COUT>
__global__ void __launch_bounds__(256) k_ln_bf16(const float* __restrict__ xin,
        const float* __restrict__ gw, const float* __restrict__ gb,
        const uint32_t* __restrict__ wb, bf16* __restrict__ out)
{
    __shared__ uint32_t sx[128 * 36];
    __shared__ uint32_t ws[2][64 * 36];

    const int tid  = threadIdx.x;
    const int lane = tid & 31;
    const int warp = tid >> 5;
    const int r    = lane >> 2;
    const int c4   = lane & 3;
    const int p0   = blockIdx.x * 128;
    const int b    = p0 >> 16;
    const int hw0  = p0 & 65535;

    {
        const int pl = tid >> 1, half = tid & 1;
        const float* xp = xin + (size_t)(b * 64 + half * 32) * HW + hw0 + pl;
        float xv[32];
        float s = 0.f, s2 = 0.f;
#pragma unroll
        for (int i = 0; i < 32; i++) {
            xv[i] = xp[(size_t)i * HW];
            s += xv[i]; s2 += xv[i] * xv[i];
        }
        s  += __shfl_xor_sync(0xffffffffu, s, 1);
        s2 += __shfl_xor_sync(0xffffffffu, s2, 1);
        const float mu   = s * (1.f / 64.f);
        const float var  = fmaxf(s2 * (1.f / 64.f) - mu * mu, 0.f);
        const float rstd = rsqrtf(var + 1e-5f);
        uint32_t* sxp = sx + pl * 36 + half * 16;
#pragma unroll
        for (int i2 = 0; i2 < 16; i2++) {
            const int c = half * 32 + 2 * i2;
            const float v0 = (xv[2*i2]   - mu) * rstd * __ldg(&gw[c])   + __ldg(&gb[c]);
            const float v1 = (xv[2*i2+1] - mu) * rstd * __ldg(&gw[c+1]) + __ldg(&gb[c+1]);
            sxp[i2] = packbf(v0, v1);
        }
    }
    // stage weight chunk 0 into ws[0] (independent of sx)
    for (int idx = tid; idx < 2048; idx += 256) {
        const int o = idx >> 5, kw = idx & 31;
        ws[0][o * 36 + kw] = wb[o * 32 + kw];
    }
    __syncthreads();

    const uint32_t* ap = sx + (warp * 16 + r) * 36 + c4;
    uint32_t areg[4][4];
#pragma unroll
    for (int kk = 0; kk < 4; kk++) {
        const int kb = kk * 8;
        areg[kk][0] = ap[kb];
        areg[kk][1] = ap[8 * 36 + kb];
        areg[kk][2] = ap[kb + 4];
        areg[kk][3] = ap[8 * 36 + kb + 4];
    }

    const int pixb = hw0 + warp * 16 + r;
    const bool evenr = (r & 1) == 0;
    const int NCH  = (COUT + 63) / 64;
    for (int chunk = 0; chunk < NCH; chunk++) {
        const int och = chunk * 64;
        const uint32_t* wcur = ws[chunk & 1];
        // prefetch next chunk into the other buffer (overlaps with MMA below)
        if (chunk + 1 < NCH) {
            uint32_t* wnxt = ws[(chunk + 1) & 1];
            const int ochn = och + 64;
            for (int idx = tid; idx < 2048; idx += 256) {
                const int o = idx >> 5, kw = idx & 31;
                wnxt[o * 36 + kw] = wb[(ochn + o) * 32 + kw];
            }
        }

        float acc[8][4];
#pragma unroll
        for (int nt = 0; nt < 8; nt++)
#pragma unroll
            for (int j = 0; j < 4; j++) acc[nt][j] = 0.f;

#pragma unroll
        for (int kk = 0; kk < 4; kk++) {
            const int kb = kk * 8 + c4;
#pragma unroll
            for (int nt = 0; nt < 8; nt++) {
                const uint32_t b0 = wcur[(nt * 8 + r) * 36 + kb];
                const uint32_t b1 = wcur[(nt * 8 + r) * 36 + kb + 4];
                mma_bf16(acc[nt], areg[kk][0], areg[kk][1], areg[kk][2], areg[kk][3],
                         b0, b1);
            }
        }

        // ---- packed store epilogue: shfl pixel-pair exchange -> STG.32
#pragma unroll
        for (int nt = 0; nt < 8; nt++) {
            const int o = och + nt * 8 + 2 * c4;
            const float pc0 = __shfl_xor_sync(0xffffffffu, acc[nt][0], 4);
            const float pc1 = __shfl_xor_sync(0xffffffffu, acc[nt][1], 4);
            const float pc2 = __shfl_xor_sync(0xffffffffu, acc[nt][2], 4);
            const float pc3 = __shfl_xor_sync(0xffffffffu, acc[nt][3], 4);
            if (evenr) {
                if ((COUT & 63) == 0 || o < COUT) {
                    uint32_t* p = (uint32_t*)(out + (size_t)(b * COUT + o) * HW + pixb);
                    p[0] = packbf(acc[nt][0], pc0);
                    p[4] = packbf(acc[nt][2], pc2);
                }
            } else {
                if ((COUT & 63) == 0 || o + 1 < COUT) {
                    uint32_t* p = (uint32_t*)(out + (size_t)(b * COUT + o + 1) * HW + pixb - 1);
                    p[0] = packbf(pc1, acc[nt][1]);
                    p[4] = packbf(pc3, acc[nt][3]);
                }
            }
        }
        __syncthreads();   // next buffer fully staged; current fully consumed
    }
}

// ---------------- K5: pout (64 x 170) bf16 MMA + residual ----------------------
__global__ void __launch_bounds__(256) k_pout_bf16(const bf16* __restrict__ y,
        const uint32_t* __restrict__ wob, const float* __restrict__ x1,
        float* __restrict__ out)
{
    __shared__ uint32_t sx2[32 * 136];   // A: [kw][px] k-pair words
    __shared__ uint32_t ws[64 * 36];     // B: [o][kw]

    const int tid  = threadIdx.x;
    const int lane = tid & 31;
    const int warp = tid >> 5;
    const int r    = lane >> 2;
    const int c4   = lane & 3;
    const int p0   = blockIdx.x * 128;
    const int b    = p0 >> 16;
    const int hw0  = p0 & 65535;

    float acc[8][4];
#pragma unroll
    for (int nt = 0; nt < 8; nt++)
#pragma unroll
        for (int j = 0; j < 4; j++) acc[nt][j] = 0.f;

    const int px2 = tid & 63;
    const int kh  = tid >> 6;
    const bf16* yp = y + (size_t)(b * HID) * HW + hw0 + px2 * 2;

    for (int kc = 0; kc < 192; kc += 64) {
        __syncthreads();
#pragma unroll
        for (int j = 0; j < 8; j++) {
            const int kw = kh * 8 + j;
            const int k0 = kc + 2 * kw;
            uint32_t u0 = 0u, u1 = 0u;
            if (k0     < HID) u0 = *(const uint32_t*)(yp + (size_t)k0 * HW);
            if (k0 + 1 < HID) u1 = *(const uint32_t*)(yp + (size_t)(k0 + 1) * HW);
            const uint32_t v0 = (u0 & 0xffffu) | (u1 << 16);
            const uint32_t v1 = (u0 >> 16)     | (u1 & 0xffff0000u);
            uint64_t pair = (uint64_t)v0 | ((uint64_t)v1 << 32);
            *(uint64_t*)(sx2 + kw * 136 + px2 * 2) = pair;
        }
        for (int idx = tid; idx < 2048; idx += 256) {
            const int o = idx >> 5, kw = idx & 31;
            ws[o * 36 + kw] = wob[o * 96 + (kc >> 1) + kw];
        }
        __syncthreads();

#pragma unroll
        for (int kk = 0; kk < 4; kk++) {
            const int kb = kk * 8 + c4;
            const uint32_t a0 = sx2[kb * 136 + warp * 16 + r];
            const uint32_t a1 = sx2[kb * 136 + warp * 16 + r + 8];
            const uint32_t a2 = sx2[(kb + 4) * 136 + warp * 16 + r];
            const uint32_t a3 = sx2[(kb + 4) * 136 + warp * 16 + r + 8];
#pragma unroll
            for (int nt = 0; nt < 8; nt++) {
                const uint32_t b0 = ws[(nt * 8 + r) * 36 + kb];
                const uint32_t b1 = ws[(nt * 8 + r) * 36 + kb + 4];
                mma_bf16(acc[nt], a0, a1, a2, a3, b0, b1);
            }
        }
    }

    const int pixb = hw0 + warp * 16 + r;
#pragma unroll
    for (int nt = 0; nt < 8; nt++) {
        const int o = nt * 8 + 2 * c4;
        const size_t g = (size_t)(b * 64 + o) * HW + pixb;
        out[g]          = x1[g]          + acc[nt][0];
        out[g + HW]     = x1[g + HW]     + acc[nt][1];
        out[g + 8]      = x1[g + 8]      + acc[nt][2];
        out[g + HW + 8] = x1[g + HW + 8] + acc[nt][3];
    }
}

// ---------------- K2/K4: depthwise 3x3, bf16, 8px x 2 rows per thread ---------
template<int CHAN>
__global__ void __launch_bounds__(256) k_dw8(const bf16* __restrict__ in,
        const float* __restrict__ wt, bf16* __restrict__ out)
{
    const int idx = blockIdx.x * 256 + threadIdx.x;      // over B*CHAN*HW/16
    const int hwo = idx & 4095;
    const int cb  = idx >> 12;
    const int ch  = cb % CHAN;
    const int h0  = (hwo >> 5) * 2;
    const int w0  = (hwo & 31) * 8;
    float wk[9];
#pragma unroll
    for (int j = 0; j < 9; j++) wk[j] = __ldg(&wt[ch * 9 + j]);
    const bf16* ip = in + ((size_t)cb << 16);

    float acc[2][8];
#pragma unroll
    for (int q = 0; q < 2; q++)
#pragma unroll
        for (int j = 0; j < 8; j++) acc[q][j] = 0.f;

#pragma unroll
    for (int kr = 0; kr < 4; kr++) {
        const int rr = h0 - 1 + kr;
        if ((unsigned)rr >= 256u) continue;
        const bf16* rp = ip + rr * Ww + w0;
        float rv[10];
        rv[0] = (w0 > 0)   ? __bfloat162float(rp[-1]) : 0.f;
        rv[9] = (w0 < 248) ? __bfloat162float(rp[8])  : 0.f;
        bf8_to_f(*(const uint4*)rp, rv + 1);
        if (kr <= 2) {
            const float k0 = wk[kr*3], k1 = wk[kr*3+1], k2 = wk[kr*3+2];
#pragma unroll
            for (int j = 0; j < 8; j++)
                acc[0][j] += k0 * rv[j] + k1 * rv[j + 1] + k2 * rv[j + 2];
        }
        if (kr >= 1) {
            const float k0 = wk[(kr-1)*3], k1 = wk[(kr-1)*3+1], k2 = wk[(kr-1)*3+2];
#pragma unroll
            for (int j = 0; j < 8; j++)
                acc[1][j] += k0 * rv[j] + k1 * rv[j + 1] + k2 * rv[j + 2];
        }
    }
    bf16* op = out + ((size_t)cb << 16) + h0 * Ww + w0;
    *(uint4*)op        = f_to_bf8(acc[0]);
    *(uint4*)(op + Ww) = f_to_bf8(acc[1]);
}

__global__ void __launch_bounds__(256) k_dwgate8(const bf16* __restrict__ in,
        const float* __restrict__ wt, bf16* __restrict__ out)
{
    const int idx = blockIdx.x * 256 + threadIdx.x;      // over B*HID*HW/16
    const int hwo = idx & 4095;
    const int cb  = idx >> 12;
    const int ch  = cb % HID;
    const int b   = cb / HID;
    const int h0  = (hwo >> 5) * 2;
    const int w0  = (hwo & 31) * 8;

    const bf16* ip1 = in + (size_t)(b * C2 + ch) * HW;
    const bf16* ip2 = ip1 + (size_t)HID * HW;

    float a1[2][8], a2[2][8];
#pragma unroll
    for (int q = 0; q < 2; q++)
#pragma unroll
        for (int j = 0; j < 8; j++) { a1[q][j] = 0.f; a2[q][j] = 0.f; }

    {
        float w1[9];
#pragma unroll
        for (int j = 0; j < 9; j++) w1[j] = __ldg(&wt[ch * 9 + j]);
#pragma unroll
        for (int kr = 0; kr < 4; kr++) {
            const int rr = h0 - 1 + kr;
            if ((unsigned)rr >= 256u) continue;
            const bf16* rp = ip1 + rr * Ww + w0;
            float rv[10];
            rv[0] = (w0 > 0)   ? __bfloat162float(rp[-1]) : 0.f;
            rv[9] = (w0 < 248) ? __bfloat162float(rp[8])  : 0.f;
            bf8_to_f(*(const uint4*)rp, rv + 1);
            if (kr <= 2) {
                const float k0 = w1[kr*3], k1 = w1[kr*3+1], k2 = w1[kr*3+2];
#pragma unroll
                for (int j = 0; j < 8; j++)
                    a1[0][j] += k0 * rv[j] + k1 * rv[j + 1] + k2 * rv[j + 2];
            }
            if (kr >= 1) {
                const float k0 = w1[(kr-1)*3], k1 = w1[(kr-1)*3+1], k2 = w1[(kr-1)*3+2];
#pragma unroll
                for (int j = 0; j < 8; j++)
                    a1[1][j] += k0 * rv[j] + k1 * rv[j + 1] + k2 * rv[j + 2];
            }
        }
    }
    {
        float w2[9];
#pragma unroll
        for (int j = 0; j < 9; j++) w2[j] = __ldg(&wt[(ch + HID) * 9 + j]);
#pragma unroll
        for (int kr = 0; kr < 4; kr++) {
            const int rr = h0 - 1 + kr;
            if ((unsigned)rr >= 256u) continue;
            const bf16* rp = ip2 + rr * Ww + w0;
            float rv[10];
            rv[0] = (w0 > 0)   ? __bfloat162float(rp[-1]) : 0.f;
            rv[9] = (w0 < 248) ? __bfloat162float(rp[8])  : 0.f;
            bf8_to_f(*(const uint4*)rp, rv + 1);
            if (kr <= 2) {
                const float k0 = w2[kr*3], k1 = w2[kr*3+1], k2 = w2[kr*3+2];
#pragma unroll
                for (int j = 0; j < 8; j++)
                    a2[0][j] += k0 * rv[j] + k1 * rv[j + 1] + k2 * rv[j + 2];
            }
            if (kr >= 1) {
                const float k0 = w2[(kr-1)*3], k1 = w2[(kr-1)*3+1], k2 = w2[(kr-1)*3+2];
#pragma unroll
                for (int j = 0; j < 8; j++)
                    a2[1][j] += k0 * rv[j] + k1 * rv[j + 1] + k2 * rv[j + 2];
            }
        }
    }

    bf16* op = out + (size_t)(b * HID + ch) * HW + h0 * Ww + w0;
#pragma unroll
    for (int q = 0; q < 2; q++) {
        float o[8];
#pragma unroll
        for (int j = 0; j < 8; j++) {
            const float ge = 0.5f * a1[q][j] * (1.0f + erff(a1[q][j] * 0.70710678118654752f));
            o[j] = ge * a2[q][j];
        }
        *(uint4*)(op + q * Ww) = f_to_bf8(o);
    }
}

// ---------------- K3: window attention, bf16 MMA, 2 windows/block (frozen) ----
#define ATT_SMEM 55296
__global__ void __launch_bounds__(256, 4) k_attn_bf16(const bf16* __restrict__ qkv,
        const float* __restrict__ temp, const float* __restrict__ pw,
        const float* __restrict__ pb, const float* __restrict__ xres,
        float* __restrict__ xout)
{
    extern __shared__ char smem[];
    uint32_t* sq = (uint32_t*)smem;
    uint32_t* sk = (uint32_t*)(smem + 18432);
    uint32_t* sv = (uint32_t*)(smem + 36864);

    const int tid  = threadIdx.x;
    const int lane = tid & 31;
    const int w    = tid >> 5;
    const int r    = lane >> 2;
    const int c4   = lane & 3;

    const int blk  = blockIdx.x;
    const int b    = blk >> 9;
    const int row0 = ((blk >> 4) & 31) * 8;
    const int col0 = (blk & 15) * 16;

    for (int i = tid; i < 2048; i += 256) {
        const int hv = i & 1, row = (i >> 1) & 7, ch = (i >> 4) & 63, s = i >> 10;
        const bf16* src = qkv + ((size_t)(b * C3 + s * 64 + ch) << 16)
                        + (row0 + row) * Ww + col0 + hv * 8;
        uint4 u = *(const uint4*)src;
        uint32_t* dst = ((s == 0) ? sq : sk) + (hv * 64 + ch) * 36 + row * 4;
        *(uint4*)dst = u;
    }
    for (int i = tid; i < 1024; i += 256) {
        const int hv = i & 1, row = (i >> 1) & 7, ch = (i >> 4) & 63;
        const bf16* src = qkv + ((size_t)(b * C3 + 128 + ch) << 16)
                        + (row0 + row) * Ww + col0 + hv * 8;
        uint4 u = *(const uint4*)src;
        *(uint4*)(sv + (hv * 64 + ch) * 36 + row * 4) = u;
    }
    __syncthreads();

#pragma unroll
    for (int it = 0; it < 2; it++) {
        const int idx = tid + it * 256;
        const int rown = idx >> 1, hw2 = idx & 1;
        uint32_t* base = ((rown < 128) ? sq : sk) + (rown & 127) * 36 + hw2 * 16;
        float v[32]; float ss = 0.f;
#pragma unroll
        for (int j = 0; j < 4; j++) {
            uint4 u = *(uint4*)(base + j * 4);
            bf8_to_f(u, v + j * 8);
        }
#pragma unroll
        for (int j = 0; j < 32; j++) ss += v[j] * v[j];
        ss += __shfl_xor_sync(0xffffffffu, ss, 1);
        float sc = 1.f / fmaxf(sqrtf(ss), 1e-12f);
        if (rown < 128) sc *= __ldg(&temp[(rown >> 5) & 1]);
#pragma unroll
        for (int j = 0; j < 4; j++) {
            float t2[8];
#pragma unroll
            for (int m = 0; m < 8; m++) t2[m] = v[j * 8 + m] * sc;
            *(uint4*)(base + j * 4) = f_to_bf8(t2);
        }
    }
    __syncthreads();

    const int win = w >> 2, h = (w >> 1) & 1, mh = w & 1;

    float acc1[4][4];
#pragma unroll
    for (int nt = 0; nt < 4; nt++)
#pragma unroll
        for (int j = 0; j < 4; j++) acc1[nt][j] = 0.f;
    {
        const uint32_t* qb = sq + (win * 64 + h * 32 + mh * 16) * 36;
        const uint32_t* kb = sk + (win * 64 + h * 32) * 36;
#pragma unroll
        for (int kk = 0; kk < 4; kk++) {
            const int ko = kk * 8 + c4;
            const uint32_t a0 = qb[r * 36 + ko];
            const uint32_t a1 = qb[(r + 8) * 36 + ko];
            const uint32_t a2 = qb[r * 36 + ko + 4];
            const uint32_t a3 = qb[(r + 8) * 36 + ko + 4];
#pragma unroll
            for (int nt = 0; nt < 4; nt++) {
                const uint32_t b0 = kb[(nt * 8 + r) * 36 + ko];
                const uint32_t b1 = kb[(nt * 8 + r) * 36 + ko + 4];
                mma_bf16(acc1[nt], a0, a1, a2, a3, b0, b1);
            }
        }
    }

    uint32_t battn[2][4];
    {
        float m1 = -1e30f, m2 = -1e30f;
#pragma unroll
        for (int nt = 0; nt < 4; nt++) {
            m1 = fmaxf(m1, fmaxf(acc1[nt][0], acc1[nt][1]));
            m2 = fmaxf(m2, fmaxf(acc1[nt][2], acc1[nt][3]));
        }
        m1 = fmaxf(m1, __shfl_xor_sync(0xffffffffu, m1, 1));
        m1 = fmaxf(m1, __shfl_xor_sync(0xffffffffu, m1, 2));
        m2 = fmaxf(m2, __shfl_xor_sync(0xffffffffu, m2, 1));
        m2 = fmaxf(m2, __shfl_xor_sync(0xffffffffu, m2, 2));
        float s1 = 0.f, s2 = 0.f;
#pragma unroll
        for (int nt = 0; nt < 4; nt++) {
            acc1[nt][0] = __expf(acc1[nt][0] - m1);
            acc1[nt][1] = __expf(acc1[nt][1] - m1);
            acc1[nt][2] = __expf(acc1[nt][2] - m2);
            acc1[nt][3] = __expf(acc1[nt][3] - m2);
            s1 += acc1[nt][0] + acc1[nt][1];
            s2 += acc1[nt][2] + acc1[nt][3];
        }
        s1 += __shfl_xor_sync(0xffffffffu, s1, 1);
        s1 += __shfl_xor_sync(0xffffffffu, s1, 2);
        s2 += __shfl_xor_sync(0xffffffffu, s2, 1);
        s2 += __shfl_xor_sync(0xffffffffu, s2, 2);
        const float i1 = 1.f / s1, i2 = 1.f / s2;
        battn[0][0] = packbf(acc1[0][0] * i1, acc1[0][1] * i1);
        battn[0][1] = packbf(acc1[1][0] * i1, acc1[1][1] * i1);
        battn[0][2] = packbf(acc1[0][2] * i2, acc1[0][3] * i2);
        battn[0][3] = packbf(acc1[1][2] * i2, acc1[1][3] * i2);
        battn[1][0] = packbf(acc1[2][0] * i1, acc1[2][1] * i1);
        battn[1][1] = packbf(acc1[3][0] * i1, acc1[3][1] * i1);
        battn[1][2] = packbf(acc1[2][2] * i2, acc1[2][3] * i2);
        battn[1][3] = packbf(acc1[3][2] * i2, acc1[3][3] * i2);
    }
    __syncthreads();

    {
        const uint32_t svb = (uint32_t)__cvta_generic_to_shared(sv)
                           + (uint32_t)((win * 64 + h * 32) * 144);
        const int erow = ((lane >> 4) & 1) * 8 + (lane & 7);
        const int dcol = ((lane >> 3) & 1) * 8;
#pragma unroll
        for (int mt = 0; mt < 4; mt++) {
            float a2c[2][4];
#pragma unroll
            for (int nt = 0; nt < 2; nt++)
#pragma unroll
                for (int j = 0; j < 4; j++) a2c[nt][j] = 0.f;
#pragma unroll
            for (int kk2 = 0; kk2 < 2; kk2++) {
                uint32_t av[4];
                ldmx4t(av, svb + (uint32_t)((kk2 * 16 + erow) * 144
                                            + (mt * 16 + dcol) * 2));
                mma_bf16(a2c[0], av[0], av[1], av[2], av[3], battn[kk2][0], battn[kk2][1]);
                mma_bf16(a2c[1], av[0], av[1], av[2], av[3], battn[kk2][2], battn[kk2][3]);
            }
            const int base0 = (win * 64 + mt * 16 + r) * 36 + h * 16 + mh * 8 + c4;
            sq[base0]              = packbf(a2c[0][0], a2c[0][1]);
            sq[base0 + 4]          = packbf(a2c[1][0], a2c[1][1]);
            sq[base0 + 8 * 36]     = packbf(a2c[0][2], a2c[0][3]);
            sq[base0 + 8 * 36 + 4] = packbf(a2c[1][2], a2c[1][3]);
        }
    }

    for (int idx = tid; idx < 2048; idx += 256) {
        const int o = idx >> 5, cw = idx & 31;
        sk[o * 36 + cw] = packbf(pw[o * 64 + cw * 2], pw[o * 64 + cw * 2 + 1]);
    }
    __syncthreads();

    {
        const int oq = w & 3;
        const uint32_t* wpb = sk + (oq * 16) * 36;
        const uint32_t* ab  = sq + (win * 64) * 36;
        uint32_t a3r[4][4];
#pragma unroll
        for (int kk = 0; kk < 4; kk++) {
            const int ko = kk * 8 + c4;
            a3r[kk][0] = wpb[r * 36 + ko];
            a3r[kk][1] = wpb[(r + 8) * 36 + ko];
            a3r[kk][2] = wpb[r * 36 + ko + 4];
            a3r[kk][3] = wpb[(r + 8) * 36 + ko + 4];
        }
        const int o1 = oq * 16 + r, o2 = o1 + 8;
        const float bv1 = __ldg(&pb[o1]), bv2 = __ldg(&pb[o2]);
        const int pcol = col0 + win * 8 + 2 * c4;
#pragma unroll
        for (int nt = 0; nt < 8; nt++) {
            float c[4] = {0.f, 0.f, 0.f, 0.f};
#pragma unroll
            for (int kk = 0; kk < 4; kk++) {
                const int ko = kk * 8 + c4;
                const uint32_t b0 = ab[(nt * 8 + r) * 36 + ko];
                const uint32_t b1 = ab[(nt * 8 + r) * 36 + ko + 4];
                mma_bf16(c, a3r[kk][0], a3r[kk][1], a3r[kk][2], a3r[kk][3], b0, b1);
            }
            const size_t g1 = ((size_t)(b * Cc + o1) << 16) + (row0 + nt) * Ww + pcol;
            const size_t g2 = ((size_t)(b * Cc + o2) << 16) + (row0 + nt) * Ww + pcol;
            float2 x1v = *(const float2*)(xres + g1);
            float2 x2v = *(const float2*)(xres + g2);
            *(float2*)(xout + g1) = make_float2(x1v.x + c[0] + bv1, x1v.y + c[1] + bv1);
            *(float2*)(xout + g2) = make_float2(x2v.x + c[2] + bv2, x2v.y + c[3] + bv2);
        }
    }
}

// ---------------- launcher ----------------------------------------------------
extern "C" void kernel_launch(void* const* d_in, const int* in_sizes, int n_in,
                              void* d_out, int out_size)
{
    const float* x     = (const float*)d_in[0];
    const float* ln1w  = (const float*)d_in[1];
    const float* ln1b  = (const float*)d_in[2];
    const float* qkvw  = (const float*)d_in[3];
    const float* qkvdw = (const float*)d_in[4];
    const float* temp  = (const float*)d_in[5];
    const float* projw = (const float*)d_in[6];
    const float* projb = (const float*)d_in[7];
    const float* ln2w  = (const float*)d_in[8];
    const float* ln2b  = (const float*)d_in[9];
    const float* pinw  = (const float*)d_in[10];
    const float* dww   = (const float*)d_in[11];
    const float* poutw = (const float*)d_in[12];
    float* out = (float*)d_out;

    bf16 *qkv, *qkv2, *mid, *y;
    float *x1;
    uint32_t *wqb, *wpb, *wob;
    cudaGetSymbolAddress((void**)&qkv,  g_qkv);
    cudaGetSymbolAddress((void**)&qkv2, g_qkv2);
    cudaGetSymbolAddress((void**)&x1,   g_x1);
    cudaGetSymbolAddress((void**)&mid,  g_mid);
    cudaGetSymbolAddress((void**)&y,    g_y);
    cudaGetSymbolAddress((void**)&wqb,  g_wqb);
    cudaGetSymbolAddress((void**)&wpb,  g_wpb);
    cudaGetSymbolAddress((void**)&wob,  g_wob);

    cudaFuncSetAttribute(k_attn_bf16,
        cudaFuncAttributeMaxDynamicSharedMemorySize, ATT_SMEM);

    k_prep<<<48, 256>>>(qkvw, pinw, poutw, wqb, wpb, wob);
    // LN1 + qkv 1x1 -> qkv (double-buffered weight staging)
    k_ln_bf16<C3><<<(Bz * HW) / 128, 256>>>(x, ln1w, ln1b, wqb, qkv);
    // depthwise 3x3 on qkv (2 rows/thread)
    k_dw8<C3><<<(Bz * C3 * HW / 16) / 256, 256>>>(qkv, qkvdw, qkv2);
    // attention + proj + residual -> x1
    k_attn_bf16<<<Bz * 32 * 16, 256, ATT_SMEM>>>(qkv2, temp, projw, projb, x, x1);
    // LN2 + pin 1x1 -> mid (double-buffered weight staging)
    k_ln_bf16<C2><<<(Bz * HW) / 128, 256>>>(x1, ln2w, ln2b, wpb, mid);
    // dwgate + GELU -> y (2 rows/thread)
    k_dwgate8<<<(Bz * HID * HW / 16) / 256, 256>>>(mid, dww, y);
    // pout + residual -> out
    k_pout_bf16<<<(Bz * HW) / 128, 256>>>(y, wob, x1, out);
}